// round 7
// baseline (speedup 1.0000x reference)
#include <cuda_runtime.h>
#include <math.h>

// MaskedLightAdaIN fused, register-resident tiles.
// x [16,64,256,256] f32, mask [16,1,256,256] f32
// out = where(mask>=0.5, x, x*scale + bias), per-(B,C) masked stats.
//
// 4096 blocks, one per quarter plane. Each thread holds its 8 float4 of x in
// REGISTERS across the stats sync, so x is read from DRAM exactly once and
// never re-touched (no SMEM tile, no L2 re-read). The four blocks of a plane
// publish partial sums to fixed slots; the last to arrive combines them in a
// fixed order (bit-deterministic) and raises a ready flag.

#define NBC     1024            // planes
#define HW      65536
#define HW4     16384           // float4 per plane
#define Q4      4096            // float4 per quarter plane
#define THREADS 512
#define EPSV    1e-8f

__device__ float    g_part[NBC][4][5];  // per-quarter: s_all, q_all, s_fg, q_fg, n_fg
__device__ unsigned g_cnt[NBC];         // arrivals; 5 == stats ready
__device__ float2   g_sb[NBC];          // scale, bias

__global__ void init_kernel()
{
    int t = threadIdx.x;
    if (t < NBC) g_cnt[t] = 0u;
}

__global__ void __launch_bounds__(THREADS, 2) fused_kernel(const float* __restrict__ x,
                                                           const float* __restrict__ mask,
                                                           float* __restrict__ out)
{
    __shared__ float red[16 * 5];
    __shared__ float bro[2];

    const int blk = blockIdx.x;
    const int p   = blk >> 2;           // plane 0..1023
    const int q   = blk & 3;            // quarter
    const int b   = p >> 6;             // batch

    const float4* __restrict__ xp = reinterpret_cast<const float4*>(x)    + (size_t)p * HW4 + q * Q4;
    const float4* __restrict__ mp = reinterpret_cast<const float4*>(mask) + (size_t)b * HW4 + q * Q4;
    float4*       __restrict__ op = reinterpret_cast<float4*>(out)        + (size_t)p * HW4 + q * Q4;

    // ---- Phase 1: load 8 float4 per thread into registers, accumulate ----
    float4 v[8];
    unsigned mbits = 0;
    float s_all = 0.f, q_all = 0.f, s_fg = 0.f, q_fg = 0.f, n_fg = 0.f;

    #pragma unroll
    for (int k = 0; k < 8; k++) {
        const int i = threadIdx.x + k * THREADS;
        float4 xv = xp[i];
        float4 mv = mp[i];
        v[k] = xv;

        unsigned m0 = (mv.x >= 0.5f), m1 = (mv.y >= 0.5f),
                 m2 = (mv.z >= 0.5f), m3 = (mv.w >= 0.5f);
        mbits |= (m0 | (m1 << 1) | (m2 << 2) | (m3 << 3)) << (4 * k);

        float w0 = (float)m0, w1 = (float)m1, w2 = (float)m2, w3 = (float)m3;
        float x0 = xv.x, x1 = xv.y, x2 = xv.z, x3 = xv.w;

        s_all += x0 + x1 + x2 + x3;
        q_all += x0*x0 + x1*x1 + x2*x2 + x3*x3;
        s_fg  += x0*w0 + x1*w1 + x2*w2 + x3*w3;
        q_fg  += x0*x0*w0 + x1*x1*w1 + x2*x2*w2 + x3*x3*w3;
        n_fg  += w0 + w1 + w2 + w3;
    }

    // ---- block reduction (16 warps, 5 values) ----
    #pragma unroll
    for (int o = 16; o > 0; o >>= 1) {
        s_all += __shfl_xor_sync(0xffffffffu, s_all, o);
        q_all += __shfl_xor_sync(0xffffffffu, q_all, o);
        s_fg  += __shfl_xor_sync(0xffffffffu, s_fg,  o);
        q_fg  += __shfl_xor_sync(0xffffffffu, q_fg,  o);
        n_fg  += __shfl_xor_sync(0xffffffffu, n_fg,  o);
    }
    const int warp = threadIdx.x >> 5;
    const int lane = threadIdx.x & 31;
    if (lane == 0) {
        red[warp*5 + 0] = s_all;
        red[warp*5 + 1] = q_all;
        red[warp*5 + 2] = s_fg;
        red[warp*5 + 3] = q_fg;
        red[warp*5 + 4] = n_fg;
    }
    __syncthreads();

    if (threadIdx.x < 32) {
        float v0 = (lane < 16) ? red[lane*5 + 0] : 0.f;
        float v1 = (lane < 16) ? red[lane*5 + 1] : 0.f;
        float v2 = (lane < 16) ? red[lane*5 + 2] : 0.f;
        float v3 = (lane < 16) ? red[lane*5 + 3] : 0.f;
        float v4 = (lane < 16) ? red[lane*5 + 4] : 0.f;
        #pragma unroll
        for (int o = 8; o > 0; o >>= 1) {
            v0 += __shfl_xor_sync(0xffffffffu, v0, o);
            v1 += __shfl_xor_sync(0xffffffffu, v1, o);
            v2 += __shfl_xor_sync(0xffffffffu, v2, o);
            v3 += __shfl_xor_sync(0xffffffffu, v3, o);
            v4 += __shfl_xor_sync(0xffffffffu, v4, o);
        }

        if (lane == 0) {
            // fixed-slot publish -> deterministic combine order
            g_part[p][q][0] = v0;
            g_part[p][q][1] = v1;
            g_part[p][q][2] = v2;
            g_part[p][q][3] = v3;
            g_part[p][q][4] = v4;
            __threadfence();
            unsigned old = atomicAdd(&g_cnt[p], 1u);

            float scale, bias;
            if (old == 3u) {
                __threadfence();
                float t0 = 0.f, t1 = 0.f, t2 = 0.f, t3 = 0.f, nf = 0.f;
                #pragma unroll
                for (int s = 0; s < 4; s++) {
                    t0 += g_part[p][s][0];
                    t1 += g_part[p][s][1];
                    t2 += g_part[p][s][2];
                    t3 += g_part[p][s][3];
                    nf += g_part[p][s][4];
                }
                float nb = (float)HW - nf;
                float s_b = t0 - t2, q_b = t1 - t3;

                float mu_f  = t2 / nf;
                float var_f = fmaxf(t3 - t2 * mu_f, 0.f) / (nf - 1.f);
                float sig_f = sqrtf(var_f);

                float mu_b  = s_b / nb;
                float var_b = fmaxf(q_b - s_b * mu_b, 0.f) / (nb - 1.f);
                float sig_b = sqrtf(var_b);

                scale = sig_f / (sig_b + EPSV);
                bias  = mu_f - mu_b * scale;

                g_sb[p] = make_float2(scale, bias);
                __threadfence();
                atomicExch(&g_cnt[p], 5u);      // stats ready
            } else {
                unsigned w;
                do {
                    __nanosleep(64);
                    w = atomicAdd(&g_cnt[p], 0u);
                } while (w != 5u);
                __threadfence();
                float2 sb = g_sb[p];
                scale = sb.x;
                bias  = sb.y;
            }
            bro[0] = scale;
            bro[1] = bias;
        }
    }
    __syncthreads();

    const float scale = bro[0];
    const float bias  = bro[1];

    // ---- Phase 2: write straight from registers ----
    #pragma unroll
    for (int k = 0; k < 8; k++) {
        const int i = threadIdx.x + k * THREADS;
        float4 xv = v[k];
        unsigned m = (mbits >> (4 * k)) & 0xFu;

        float4 ov;
        ov.x = (m & 1u) ? xv.x : fmaf(xv.x, scale, bias);
        ov.y = (m & 2u) ? xv.y : fmaf(xv.y, scale, bias);
        ov.z = (m & 4u) ? xv.z : fmaf(xv.z, scale, bias);
        ov.w = (m & 8u) ? xv.w : fmaf(xv.w, scale, bias);

        op[i] = ov;
    }
}

extern "C" void kernel_launch(void* const* d_in, const int* in_sizes, int n_in,
                              void* d_out, int out_size)
{
    const float* x    = (const float*)d_in[0];
    const float* mask = (const float*)d_in[1];
    float* out        = (float*)d_out;

    init_kernel<<<1, 1024>>>();
    fused_kernel<<<4 * NBC, THREADS>>>(x, mask, out);
}

// round 8
// speedup vs baseline: 1.0763x; 1.0763x over previous
#include <cuda_runtime.h>
#include <math.h>

// MaskedLightAdaIN, optimized two-pass pipeline (no atomics, deterministic):
//   1) stats_kernel:    4096 blocks, one per quarter-plane; fixed-slot partials
//   2) finalize_kernel: 1024 threads, one per plane; combine slots -> scale/bias
//   3) apply_kernel:    elementwise, streaming loads/stores
// x [16,64,256,256] f32, mask [16,1,256,256] f32

#define NBC     1024            // planes (B*C)
#define HW      65536
#define HW4     16384           // float4 per plane
#define Q4      4096            // float4 per quarter plane
#define EPSV    1e-8f

__device__ float  g_part[NBC][4][5];  // per-quarter: s_all, q_all, s_fg, q_fg, n_fg
__device__ float2 g_sb[NBC];          // scale, bias

// ---------------------------------------------------------------------------
// Pass 1: partial sums per quarter-plane. 256 threads x 16 float4.
// ---------------------------------------------------------------------------
__global__ void __launch_bounds__(256) stats_kernel(const float* __restrict__ x,
                                                    const float* __restrict__ mask)
{
    const int blk = blockIdx.x;         // 0..4095
    const int p   = blk >> 2;           // plane
    const int q   = blk & 3;            // quarter
    const int b   = p >> 6;             // batch

    const float4* __restrict__ xp = reinterpret_cast<const float4*>(x)    + (size_t)p * HW4 + q * Q4;
    const float4* __restrict__ mp = reinterpret_cast<const float4*>(mask) + (size_t)b * HW4 + q * Q4;

    float s_all = 0.f, q_all = 0.f, s_fg = 0.f, q_fg = 0.f, n_fg = 0.f;

    #pragma unroll 4
    for (int k = 0; k < 16; k++) {
        const int i = threadIdx.x + (k << 8);
        float4 xv = __ldcs(&xp[i]);     // streaming: x won't be re-read before apply
        float4 mv = mp[i];              // mask: keep cached (64x reuse per batch)

        float w0 = (mv.x >= 0.5f) ? 1.f : 0.f;
        float w1 = (mv.y >= 0.5f) ? 1.f : 0.f;
        float w2 = (mv.z >= 0.5f) ? 1.f : 0.f;
        float w3 = (mv.w >= 0.5f) ? 1.f : 0.f;
        float x0 = xv.x, x1 = xv.y, x2 = xv.z, x3 = xv.w;

        s_all += x0 + x1 + x2 + x3;
        q_all += x0*x0 + x1*x1 + x2*x2 + x3*x3;
        s_fg  += x0*w0 + x1*w1 + x2*w2 + x3*w3;
        q_fg  += x0*x0*w0 + x1*x1*w1 + x2*x2*w2 + x3*x3*w3;
        n_fg  += w0 + w1 + w2 + w3;
    }

    // warp reduce (5 values)
    #pragma unroll
    for (int o = 16; o > 0; o >>= 1) {
        s_all += __shfl_xor_sync(0xffffffffu, s_all, o);
        q_all += __shfl_xor_sync(0xffffffffu, q_all, o);
        s_fg  += __shfl_xor_sync(0xffffffffu, s_fg,  o);
        q_fg  += __shfl_xor_sync(0xffffffffu, q_fg,  o);
        n_fg  += __shfl_xor_sync(0xffffffffu, n_fg,  o);
    }

    __shared__ float red[8][5];
    const int warp = threadIdx.x >> 5;
    const int lane = threadIdx.x & 31;
    if (lane == 0) {
        red[warp][0] = s_all; red[warp][1] = q_all;
        red[warp][2] = s_fg;  red[warp][3] = q_fg;
        red[warp][4] = n_fg;
    }
    __syncthreads();

    if (threadIdx.x < 32) {
        float v0 = (lane < 8) ? red[lane][0] : 0.f;
        float v1 = (lane < 8) ? red[lane][1] : 0.f;
        float v2 = (lane < 8) ? red[lane][2] : 0.f;
        float v3 = (lane < 8) ? red[lane][3] : 0.f;
        float v4 = (lane < 8) ? red[lane][4] : 0.f;
        #pragma unroll
        for (int o = 4; o > 0; o >>= 1) {
            v0 += __shfl_xor_sync(0xffffffffu, v0, o);
            v1 += __shfl_xor_sync(0xffffffffu, v1, o);
            v2 += __shfl_xor_sync(0xffffffffu, v2, o);
            v3 += __shfl_xor_sync(0xffffffffu, v3, o);
            v4 += __shfl_xor_sync(0xffffffffu, v4, o);
        }
        if (lane == 0) {
            g_part[p][q][0] = v0;
            g_part[p][q][1] = v1;
            g_part[p][q][2] = v2;
            g_part[p][q][3] = v3;
            g_part[p][q][4] = v4;
        }
    }
}

// ---------------------------------------------------------------------------
// Pass 2: combine the 4 quarter slots per plane (fixed order -> deterministic)
// ---------------------------------------------------------------------------
__global__ void finalize_kernel()
{
    const int p = blockIdx.x * blockDim.x + threadIdx.x;
    if (p >= NBC) return;

    float t0 = 0.f, t1 = 0.f, t2 = 0.f, t3 = 0.f, nf = 0.f;
    #pragma unroll
    for (int s = 0; s < 4; s++) {
        t0 += g_part[p][s][0];
        t1 += g_part[p][s][1];
        t2 += g_part[p][s][2];
        t3 += g_part[p][s][3];
        nf += g_part[p][s][4];
    }
    float nb  = (float)HW - nf;
    float s_b = t0 - t2, q_b = t1 - t3;

    float mu_f  = t2 / nf;
    float var_f = fmaxf(t3 - t2 * mu_f, 0.f) / (nf - 1.f);
    float sig_f = sqrtf(var_f);

    float mu_b  = s_b / nb;
    float var_b = fmaxf(q_b - s_b * mu_b, 0.f) / (nb - 1.f);
    float sig_b = sqrtf(var_b);

    float scale = sig_f / (sig_b + EPSV);
    float bias  = mu_f - mu_b * scale;
    g_sb[p] = make_float2(scale, bias);
}

// ---------------------------------------------------------------------------
// Pass 3: elementwise apply. 16 blocks per plane, 4 float4 per thread.
// ---------------------------------------------------------------------------
__global__ void __launch_bounds__(256) apply_kernel(const float* __restrict__ x,
                                                    const float* __restrict__ mask,
                                                    float* __restrict__ out)
{
    const int blk = blockIdx.x;         // 0..16383
    const int p   = blk >> 4;           // plane
    const int seg = blk & 15;           // 1024-float4 segment within plane
    const int b   = p >> 6;             // batch

    const size_t xoff = (size_t)p * HW4 + (size_t)seg * 1024;
    const size_t moff = (size_t)b * HW4 + (size_t)seg * 1024;

    const float4* __restrict__ xp = reinterpret_cast<const float4*>(x)    + xoff;
    const float4* __restrict__ mp = reinterpret_cast<const float4*>(mask) + moff;
    float4*       __restrict__ op = reinterpret_cast<float4*>(out)        + xoff;

    const float2 sb = g_sb[p];          // uniform per block -> broadcast load
    const float scale = sb.x;
    const float bias  = sb.y;

    #pragma unroll
    for (int k = 0; k < 4; k++) {
        const int i = threadIdx.x + (k << 8);
        float4 xv = __ldcs(&xp[i]);     // streaming read
        float4 mv = mp[i];              // cached (reused across channels)

        float4 ov;
        ov.x = (mv.x >= 0.5f) ? xv.x : fmaf(xv.x, scale, bias);
        ov.y = (mv.y >= 0.5f) ? xv.y : fmaf(xv.y, scale, bias);
        ov.z = (mv.z >= 0.5f) ? xv.z : fmaf(xv.z, scale, bias);
        ov.w = (mv.w >= 0.5f) ? xv.w : fmaf(xv.w, scale, bias);

        __stcs(&op[i], ov);             // streaming write: out never re-read
    }
}

extern "C" void kernel_launch(void* const* d_in, const int* in_sizes, int n_in,
                              void* d_out, int out_size)
{
    const float* x    = (const float*)d_in[0];
    const float* mask = (const float*)d_in[1];
    float* out        = (float*)d_out;

    stats_kernel<<<4 * NBC, 256>>>(x, mask);
    finalize_kernel<<<4, 256>>>();
    apply_kernel<<<16 * NBC, 256>>>(x, mask, out);
}